// round 1
// baseline (speedup 1.0000x reference)
#include <cuda_runtime.h>

// KohonenSOM pairwise L2 distance: out[b][n] = || x[b] - w[n] ||_2
// x: [B, 32] fp32, w: [N, 32] fp32, out: [B, N] fp32
// Strategy: tiled fp32 "GEMM" computing cross = x . w, plus norms, epilogue sqrt.
// Tile: 128 (M) x 64 (N), 256 threads, 8x4 per-thread micro-tile, K=32 resident.

#define BM 128
#define BN 64
#define DD 32
#define TM 8
#define TN 4
#define NTHREADS 256

__global__ __launch_bounds__(NTHREADS)
void som_dist_kernel(const float* __restrict__ x,
                     const float* __restrict__ w,
                     float* __restrict__ out,
                     int B, int N)
{
    __shared__ float xsT[DD][BM];   // transposed x tile: [k][m]
    __shared__ float wsT[DD][BN];   // transposed w tile: [k][n]
    __shared__ float xs2[BM];       // ||x_m||^2
    __shared__ float ws2[BN];       // ||w_n||^2

    const int tid = threadIdx.x;
    const int m0 = blockIdx.y * BM;
    const int n0 = blockIdx.x * BN;

    // ---- Load x tile (BM x 32) as float4, store transposed ----
    // BM*DD/4 = 1024 float4 / 256 threads = 4 per thread
    #pragma unroll
    for (int i = 0; i < (BM * DD) / (4 * NTHREADS); ++i) {
        int idx = tid + i * NTHREADS;
        int row = idx / (DD / 4);
        int c4  = idx % (DD / 4);
        int gm  = m0 + row;
        float4 v = make_float4(0.f, 0.f, 0.f, 0.f);
        if (gm < B)
            v = *reinterpret_cast<const float4*>(x + (size_t)gm * DD + c4 * 4);
        xsT[c4 * 4 + 0][row] = v.x;
        xsT[c4 * 4 + 1][row] = v.y;
        xsT[c4 * 4 + 2][row] = v.z;
        xsT[c4 * 4 + 3][row] = v.w;
    }

    // ---- Load w tile (BN x 32) as float4, store transposed ----
    // BN*DD/4 = 512 float4 / 256 threads = 2 per thread
    #pragma unroll
    for (int i = 0; i < (BN * DD) / (4 * NTHREADS); ++i) {
        int idx = tid + i * NTHREADS;
        int row = idx / (DD / 4);
        int c4  = idx % (DD / 4);
        int gn  = n0 + row;
        float4 v = make_float4(0.f, 0.f, 0.f, 0.f);
        if (gn < N)
            v = *reinterpret_cast<const float4*>(w + (size_t)gn * DD + c4 * 4);
        wsT[c4 * 4 + 0][row] = v.x;
        wsT[c4 * 4 + 1][row] = v.y;
        wsT[c4 * 4 + 2][row] = v.z;
        wsT[c4 * 4 + 3][row] = v.w;
    }
    __syncthreads();

    // ---- Cooperative norm computation (conflict-free LDS: stride BM/BN) ----
    if (tid < BM) {
        float s = 0.f;
        #pragma unroll
        for (int k = 0; k < DD; ++k) {
            float v = xsT[k][tid];
            s = fmaf(v, v, s);
        }
        xs2[tid] = s;
    } else if (tid < BM + BN) {
        int c = tid - BM;
        float s = 0.f;
        #pragma unroll
        for (int k = 0; k < DD; ++k) {
            float v = wsT[k][c];
            s = fmaf(v, v, s);
        }
        ws2[c] = s;
    }
    __syncthreads();

    // ---- Main accumulation: 8x4 micro-tile over K=32 (fully unrolled) ----
    const int tn = tid & 15;    // 16 n-groups * 4  = 64 cols
    const int tm = tid >> 4;    // 16 m-groups * 8  = 128 rows

    float acc[TM][TN];
    #pragma unroll
    for (int i = 0; i < TM; ++i)
        #pragma unroll
        for (int j = 0; j < TN; ++j)
            acc[i][j] = 0.f;

    #pragma unroll
    for (int k = 0; k < DD; ++k) {
        float a[TM], b[TN];
        *reinterpret_cast<float4*>(&a[0]) = *reinterpret_cast<const float4*>(&xsT[k][tm * TM]);
        *reinterpret_cast<float4*>(&a[4]) = *reinterpret_cast<const float4*>(&xsT[k][tm * TM + 4]);
        *reinterpret_cast<float4*>(&b[0]) = *reinterpret_cast<const float4*>(&wsT[k][tn * TN]);
        #pragma unroll
        for (int i = 0; i < TM; ++i)
            #pragma unroll
            for (int j = 0; j < TN; ++j)
                acc[i][j] = fmaf(a[i], b[j], acc[i][j]);
    }

    // ---- Epilogue: dist = sqrt(max(x2 + w2 - 2*cross, 0)) ----
    float w2v[TN];
    *reinterpret_cast<float4*>(&w2v[0]) = *reinterpret_cast<const float4*>(&ws2[tn * TN]);

    const int gn = n0 + tn * TN;

    #pragma unroll
    for (int i = 0; i < TM; ++i) {
        int gm = m0 + tm * TM + i;
        if (gm >= B) continue;
        float xv = xs2[tm * TM + i];
        float r[TN];
        #pragma unroll
        for (int j = 0; j < TN; ++j) {
            float sq = fmaxf(fmaf(-2.f, acc[i][j], xv + w2v[j]), 0.f);
            // sqrt via one MUFU.RSQ: sq * rsqrt(sq); guard sq==0
            r[j] = (sq > 0.f) ? sq * rsqrtf(sq) : 0.f;
        }
        if (gn + TN <= N) {
            float4 v = make_float4(r[0], r[1], r[2], r[3]);
            *reinterpret_cast<float4*>(out + (size_t)gm * N + gn) = v;
        } else {
            #pragma unroll
            for (int j = 0; j < TN; ++j)
                if (gn + j < N) out[(size_t)gm * N + gn + j] = r[j];
        }
    }
}

extern "C" void kernel_launch(void* const* d_in, const int* in_sizes, int n_in,
                              void* d_out, int out_size)
{
    const float* x = (const float*)d_in[0];   // [B, 32]
    const float* w = (const float*)d_in[1];   // [N, 32]
    float* out = (float*)d_out;               // [B, N]

    int B = in_sizes[0] / DD;
    int N = in_sizes[1] / DD;

    dim3 grid((N + BN - 1) / BN, (B + BM - 1) / BM);
    som_dist_kernel<<<grid, NTHREADS>>>(x, w, out, B, N);
}

// round 4
// speedup vs baseline: 1.8889x; 1.8889x over previous
#include <cuda_runtime.h>
#include <cstdint>

// KohonenSOM pairwise L2 distance via warp-level tf32 mma.sync (HMMA path,
// compiles for baseline compute_103 — tcgen05 is blocked by the harness's
// virtual-arch PTX target).
//
// out[b][n] = sqrt(max(||x_b||^2 + ||w_n||^2 - 2 x_b.w_n, 0))
// Inputs rounded to tf32 (cvt.rna) at smem-stage time; norms computed from the
// ROUNDED values so dist == ||x~ - w~|| exactly (elementwise err ~1e-4).
//
// CTA tile: 128(M) x 128(N), K=32. 8 warps in 2(M) x 4(N) grid, each warp
// computes 64x32 via 4x4 m16n8k8 atoms, 4 K-steps. Epilogue fuses norms + sqrt
// and stores float2 directly from the accumulator fragment layout.

#define TILE_M 128
#define TILE_N 128
#define DD 32
#define NTH 256
#define SP 36   // smem row pitch in floats (conflict-free fragment loads)

static __device__ __forceinline__ uint32_t f2tf32(float f) {
    uint32_t r;
    asm("cvt.rna.tf32.f32 %0, %1;" : "=r"(r) : "f"(f));
    return r;
}

static __device__ __forceinline__ void mma_tf32(float* d,
                                                const uint32_t* a,
                                                const uint32_t* b) {
    asm volatile(
        "mma.sync.aligned.m16n8k8.row.col.f32.tf32.tf32.f32 "
        "{%0,%1,%2,%3}, {%4,%5,%6,%7}, {%8,%9}, {%0,%1,%2,%3};"
        : "+f"(d[0]), "+f"(d[1]), "+f"(d[2]), "+f"(d[3])
        : "r"(a[0]), "r"(a[1]), "r"(a[2]), "r"(a[3]),
          "r"(b[0]), "r"(b[1]));
}

static __device__ __forceinline__ float sqrt_approx(float v) {
    float r;
    asm("sqrt.approx.f32 %0, %1;" : "=f"(r) : "f"(v));
    return r;
}

__global__ __launch_bounds__(NTH, 2)
void som_mma_kernel(const float* __restrict__ x,
                    const float* __restrict__ w,
                    float* __restrict__ out,
                    int B, int N)
{
    __shared__ float sX[TILE_M * SP];   // tf32-rounded x tile [128][36]
    __shared__ float sW[TILE_N * SP];   // tf32-rounded w tile [128][36]
    __shared__ float xs2[TILE_M];
    __shared__ float ws2[TILE_N];

    const int tid = threadIdx.x;
    const int n0  = blockIdx.x * TILE_N;
    const int m0  = blockIdx.y * TILE_M;

    // ---- Stage tiles into smem, rounding to tf32 (coalesced float4 loads) ----
    #pragma unroll
    for (int i = 0; i < (TILE_M * DD) / (4 * NTH); ++i) {
        int f4  = tid + i * NTH;
        int row = f4 >> 3;
        int c4  = f4 & 7;
        int gm  = m0 + row;
        float4 v = make_float4(0.f, 0.f, 0.f, 0.f);
        if (gm < B)
            v = *reinterpret_cast<const float4*>(x + (size_t)gm * DD + c4 * 4);
        uint4 t;
        t.x = f2tf32(v.x); t.y = f2tf32(v.y); t.z = f2tf32(v.z); t.w = f2tf32(v.w);
        *reinterpret_cast<uint4*>(&sX[row * SP + c4 * 4]) = t;
    }
    #pragma unroll
    for (int i = 0; i < (TILE_N * DD) / (4 * NTH); ++i) {
        int f4  = tid + i * NTH;
        int row = f4 >> 3;
        int c4  = f4 & 7;
        int gn  = n0 + row;
        float4 v = make_float4(0.f, 0.f, 0.f, 0.f);
        if (gn < N)
            v = *reinterpret_cast<const float4*>(w + (size_t)gn * DD + c4 * 4);
        uint4 t;
        t.x = f2tf32(v.x); t.y = f2tf32(v.y); t.z = f2tf32(v.z); t.w = f2tf32(v.w);
        *reinterpret_cast<uint4*>(&sW[row * SP + c4 * 4]) = t;
    }
    __syncthreads();

    // ---- Norms from the ROUNDED values (consistency => dist = ||x~-w~||) ----
    {
        const float* src = (tid < TILE_M) ? &sX[tid * SP] : &sW[(tid - TILE_M) * SP];
        float s = 0.f;
        #pragma unroll
        for (int k = 0; k < DD; ++k) {
            float v = src[k];
            s = fmaf(v, v, s);
        }
        if (tid < TILE_M) xs2[tid] = s;
        else              ws2[tid - TILE_M] = s;
    }
    __syncthreads();

    // ---- Warp tiling: 2(M) x 4(N) warps; warp tile 64x32 = 4x4 m16n8k8 atoms ----
    const int lane = tid & 31;
    const int wid  = tid >> 5;
    const int wm   = wid & 1;          // 0..1  -> M offset wm*64
    const int wn   = wid >> 1;         // 0..3  -> N offset wn*32
    const int g    = lane >> 2;        // group id (row/col within atom)
    const int t    = lane & 3;         // thread in group (k index)

    const uint32_t* uX = reinterpret_cast<const uint32_t*>(sX);
    const uint32_t* uW = reinterpret_cast<const uint32_t*>(sW);

    float acc[4][4][4];
    #pragma unroll
    for (int ma = 0; ma < 4; ++ma)
        #pragma unroll
        for (int na = 0; na < 4; ++na)
            #pragma unroll
            for (int r = 0; r < 4; ++r)
                acc[ma][na][r] = 0.f;

    #pragma unroll
    for (int ks = 0; ks < 4; ++ks) {
        const int kc = ks * 8 + t;
        uint32_t afr[4][4];
        #pragma unroll
        for (int ma = 0; ma < 4; ++ma) {
            int r = wm * 64 + ma * 16 + g;
            afr[ma][0] = uX[r * SP + kc];
            afr[ma][1] = uX[(r + 8) * SP + kc];
            afr[ma][2] = uX[r * SP + kc + 4];
            afr[ma][3] = uX[(r + 8) * SP + kc + 4];
        }
        uint32_t bfr[4][2];
        #pragma unroll
        for (int na = 0; na < 4; ++na) {
            int c = wn * 32 + na * 8 + g;
            bfr[na][0] = uW[c * SP + kc];
            bfr[na][1] = uW[c * SP + kc + 4];
        }
        #pragma unroll
        for (int ma = 0; ma < 4; ++ma)
            #pragma unroll
            for (int na = 0; na < 4; ++na)
                mma_tf32(acc[ma][na], afr[ma], bfr[na]);
    }

    // ---- Epilogue: fragment c{0,1}=(row g, cols 2t,2t+1), c{2,3}=(row g+8) ----
    #pragma unroll
    for (int ma = 0; ma < 4; ++ma) {
        const int mi0 = wm * 64 + ma * 16 + g;       // local row of c0/c1
        const float x2a = xs2[mi0];
        const float x2b = xs2[mi0 + 8];
        const int gm0 = m0 + mi0;
        #pragma unroll
        for (int na = 0; na < 4; ++na) {
            const int ci = wn * 32 + na * 8 + 2 * t;  // local col
            const int gc = n0 + ci;
            float2 w2 = *reinterpret_cast<const float2*>(&ws2[ci]);

            float s0 = fmaxf(fmaf(-2.f, acc[ma][na][0], x2a + w2.x), 0.f);
            float s1 = fmaxf(fmaf(-2.f, acc[ma][na][1], x2a + w2.y), 0.f);
            float s2 = fmaxf(fmaf(-2.f, acc[ma][na][2], x2b + w2.x), 0.f);
            float s3 = fmaxf(fmaf(-2.f, acc[ma][na][3], x2b + w2.y), 0.f);

            float2 d01 = make_float2(sqrt_approx(s0), sqrt_approx(s1));
            float2 d23 = make_float2(sqrt_approx(s2), sqrt_approx(s3));

            if (gc < N) {  // N even, gc even -> float2 never straddles N
                if (gm0 < B)
                    *reinterpret_cast<float2*>(out + (size_t)gm0 * N + gc) = d01;
                if (gm0 + 8 < B)
                    *reinterpret_cast<float2*>(out + (size_t)(gm0 + 8) * N + gc) = d23;
            }
        }
    }
}

extern "C" void kernel_launch(void* const* d_in, const int* in_sizes, int n_in,
                              void* d_out, int out_size)
{
    const float* x = (const float*)d_in[0];   // [B, 32]
    const float* w = (const float*)d_in[1];   // [N, 32]
    float* out = (float*)d_out;               // [B, N]

    int B = in_sizes[0] / DD;
    int N = in_sizes[1] / DD;

    dim3 grid((N + TILE_N - 1) / TILE_N, (B + TILE_M - 1) / TILE_M);
    som_mma_kernel<<<grid, NTH>>>(x, w, out, B, N);
}

// round 5
// speedup vs baseline: 1.9676x; 1.0417x over previous
#include <cuda_runtime.h>
#include <cstdint>

// KohonenSOM pairwise L2 distance via warp-level tf32 mma.sync.
// out[b][n] = sqrt(max(||x_b||^2 + ||w_n||^2 - 2 x_b.w_n, 0))
// Inputs rounded to tf32 at smem-stage; norms computed from ROUNDED values so
// dist == ||x~ - w~|| exactly (elementwise err ~1e-4).
//
// CTA tile 128x128, K=32, 8 warps (2M x 4N), warp tile 64x32 = 4x4 m16n8k8.
// R5 change: epilogue restages each warp's 16x32 chunk into (dead) sX smem and
// stores with fully-packed STG.128 (128B contiguous per 8 lanes) instead of
// scattered STG.64 — halves L1tex store wavefronts and store instruction count.

#define TILE_M 128
#define TILE_N 128
#define DD 32
#define NTH 256
#define SP 36   // smem row pitch in floats (conflict-free fragment loads)

static __device__ __forceinline__ uint32_t f2tf32(float f) {
    uint32_t r;
    asm("cvt.rna.tf32.f32 %0, %1;" : "=r"(r) : "f"(f));
    return r;
}

static __device__ __forceinline__ void mma_tf32(float* d,
                                                const uint32_t* a,
                                                const uint32_t* b) {
    asm volatile(
        "mma.sync.aligned.m16n8k8.row.col.f32.tf32.tf32.f32 "
        "{%0,%1,%2,%3}, {%4,%5,%6,%7}, {%8,%9}, {%0,%1,%2,%3};"
        : "+f"(d[0]), "+f"(d[1]), "+f"(d[2]), "+f"(d[3])
        : "r"(a[0]), "r"(a[1]), "r"(a[2]), "r"(a[3]),
          "r"(b[0]), "r"(b[1]));
}

static __device__ __forceinline__ float sqrt_approx(float v) {
    float r;
    asm("sqrt.approx.f32 %0, %1;" : "=f"(r) : "f"(v));
    return r;
}

__global__ __launch_bounds__(NTH, 2)
void som_mma_kernel(const float* __restrict__ x,
                    const float* __restrict__ w,
                    float* __restrict__ out,
                    int B, int N)
{
    __shared__ float sX[TILE_M * SP];   // tf32-rounded x tile; reused as C stage
    __shared__ float sW[TILE_N * SP];   // tf32-rounded w tile
    __shared__ float xs2[TILE_M];
    __shared__ float ws2[TILE_N];

    const int tid = threadIdx.x;
    const int n0  = blockIdx.x * TILE_N;
    const int m0  = blockIdx.y * TILE_M;

    // ---- Stage tiles into smem, rounding to tf32 (coalesced float4 loads) ----
    #pragma unroll
    for (int i = 0; i < (TILE_M * DD) / (4 * NTH); ++i) {
        int f4  = tid + i * NTH;
        int row = f4 >> 3;
        int c4  = f4 & 7;
        int gm  = m0 + row;
        float4 v = make_float4(0.f, 0.f, 0.f, 0.f);
        if (gm < B)
            v = *reinterpret_cast<const float4*>(x + (size_t)gm * DD + c4 * 4);
        uint4 t;
        t.x = f2tf32(v.x); t.y = f2tf32(v.y); t.z = f2tf32(v.z); t.w = f2tf32(v.w);
        *reinterpret_cast<uint4*>(&sX[row * SP + c4 * 4]) = t;
    }
    #pragma unroll
    for (int i = 0; i < (TILE_N * DD) / (4 * NTH); ++i) {
        int f4  = tid + i * NTH;
        int row = f4 >> 3;
        int c4  = f4 & 7;
        int gn  = n0 + row;
        float4 v = make_float4(0.f, 0.f, 0.f, 0.f);
        if (gn < N)
            v = *reinterpret_cast<const float4*>(w + (size_t)gn * DD + c4 * 4);
        uint4 t;
        t.x = f2tf32(v.x); t.y = f2tf32(v.y); t.z = f2tf32(v.z); t.w = f2tf32(v.w);
        *reinterpret_cast<uint4*>(&sW[row * SP + c4 * 4]) = t;
    }
    __syncthreads();

    // ---- Norms from the ROUNDED values ----
    {
        const float* src = (tid < TILE_M) ? &sX[tid * SP] : &sW[(tid - TILE_M) * SP];
        float s = 0.f;
        #pragma unroll
        for (int k = 0; k < DD; ++k) {
            float v = src[k];
            s = fmaf(v, v, s);
        }
        if (tid < TILE_M) xs2[tid] = s;
        else              ws2[tid - TILE_M] = s;
    }
    __syncthreads();

    // ---- Warp tiling: 2(M) x 4(N) warps; warp tile 64x32 = 4x4 m16n8k8 ----
    const int lane = tid & 31;
    const int wid  = tid >> 5;
    const int wm   = wid & 1;          // M offset wm*64
    const int wn   = wid >> 1;         // N offset wn*32
    const int g    = lane >> 2;        // group id
    const int t    = lane & 3;         // thread in group

    const uint32_t* uX = reinterpret_cast<const uint32_t*>(sX);
    const uint32_t* uW = reinterpret_cast<const uint32_t*>(sW);

    float acc[4][4][4];
    #pragma unroll
    for (int ma = 0; ma < 4; ++ma)
        #pragma unroll
        for (int na = 0; na < 4; ++na)
            #pragma unroll
            for (int r = 0; r < 4; ++r)
                acc[ma][na][r] = 0.f;

    #pragma unroll
    for (int ks = 0; ks < 4; ++ks) {
        const int kc = ks * 8 + t;
        uint32_t afr[4][4];
        #pragma unroll
        for (int ma = 0; ma < 4; ++ma) {
            int r = wm * 64 + ma * 16 + g;
            afr[ma][0] = uX[r * SP + kc];
            afr[ma][1] = uX[(r + 8) * SP + kc];
            afr[ma][2] = uX[r * SP + kc + 4];
            afr[ma][3] = uX[(r + 8) * SP + kc + 4];
        }
        uint32_t bfr[4][2];
        #pragma unroll
        for (int na = 0; na < 4; ++na) {
            int c = wn * 32 + na * 8 + g;
            bfr[na][0] = uW[c * SP + kc];
            bfr[na][1] = uW[c * SP + kc + 4];
        }
        #pragma unroll
        for (int ma = 0; ma < 4; ++ma)
            #pragma unroll
            for (int na = 0; na < 4; ++na)
                mma_tf32(acc[ma][na], afr[ma], bfr[na]);
    }

    // ---- Epilogue: restage 16x32 chunks in smem, packed STG.128 out ----
    __syncthreads();                         // sX/sW tiles dead -> reuse sX
    float* st = sX + wid * (16 * SP);        // per-warp 16x36 stage (exactly fits)

    const int srow = lane >> 3;              // 0..3: row-within-quad for stores
    const int c4   = (lane & 7) * 4;         // 0..28: col for float4 store
    const float4 w2 = *reinterpret_cast<const float4*>(&ws2[wn * 32 + c4]);
    const int gc = n0 + wn * 32 + c4;        // N,c4 mult of 4 -> all-or-none
    const bool nok = gc < N;

    #pragma unroll
    for (int ma = 0; ma < 4; ++ma) {
        // stage this warp's 16x32 chunk (rows g and g+8 of the chunk)
        #pragma unroll
        for (int na = 0; na < 4; ++na) {
            const int c = na * 8 + 2 * t;
            *reinterpret_cast<float2*>(&st[g * SP + c]) =
                make_float2(acc[ma][na][0], acc[ma][na][1]);
            *reinterpret_cast<float2*>(&st[(g + 8) * SP + c]) =
                make_float2(acc[ma][na][2], acc[ma][na][3]);
        }
        __syncwarp();
        // store 16 rows: 4 iterations x 4 rows, 128B contiguous per 8 lanes
        #pragma unroll
        for (int it = 0; it < 4; ++it) {
            const int lr = it * 4 + srow;
            const int mi = wm * 64 + ma * 16 + lr;
            const int gm = m0 + mi;
            const float x2 = xs2[mi];
            float4 cr = *reinterpret_cast<const float4*>(&st[lr * SP + c4]);
            float4 d;
            d.x = sqrt_approx(fmaxf(fmaf(-2.f, cr.x, x2 + w2.x), 0.f));
            d.y = sqrt_approx(fmaxf(fmaf(-2.f, cr.y, x2 + w2.y), 0.f));
            d.z = sqrt_approx(fmaxf(fmaf(-2.f, cr.z, x2 + w2.z), 0.f));
            d.w = sqrt_approx(fmaxf(fmaf(-2.f, cr.w, x2 + w2.w), 0.f));
            if (nok && gm < B)
                *reinterpret_cast<float4*>(out + (size_t)gm * N + gc) = d;
        }
        __syncwarp();
    }
}

extern "C" void kernel_launch(void* const* d_in, const int* in_sizes, int n_in,
                              void* d_out, int out_size)
{
    const float* x = (const float*)d_in[0];   // [B, 32]
    const float* w = (const float*)d_in[1];   // [N, 32]
    float* out = (float*)d_out;               // [B, N]

    int B = in_sizes[0] / DD;
    int N = in_sizes[1] / DD;

    dim3 grid((N + TILE_N - 1) / TILE_N, (B + TILE_M - 1) / TILE_M);
    som_mma_kernel<<<grid, NTH>>>(x, w, out, B, N);
}

// round 7
// speedup vs baseline: 2.0412x; 1.0374x over previous
#include <cuda_runtime.h>
#include <cstdint>

// KohonenSOM pairwise L2 distance via warp-level tf32 mma.sync.
// out[b][n] = sqrt(max(||x_b||^2 + ||w_n||^2 - 2 x_b.w_n, 0))
// Inputs rounded to tf32 at smem-stage; norms computed from ROUNDED values.
//
// CTA tile 128x128, K=32, 8 warps (2M x 4N), warp tile 64x32 = 4x4 m16n8k8.
// R6: (a) k-permutation so fragment pairs are smem-adjacent -> LDS.64 loads
//     (mainloop LDS instr count halved; pitch 40 => conflict-free);
//     (b) norms computed during staging via 8-lane shfl butterfly (no LDS pass);
//     (c) R5 packed STG.128 epilogue kept.

#define TILE_M 128
#define TILE_N 128
#define DD 32
#define NTH 256
#define SP 40   // smem row pitch in floats: conflict-free LDS.64 fragment loads

static __device__ __forceinline__ uint32_t f2tf32(float f) {
    uint32_t r;
    asm("cvt.rna.tf32.f32 %0, %1;" : "=r"(r) : "f"(f));
    return r;
}

static __device__ __forceinline__ void mma_tf32(float* d,
                                                const uint32_t* a,
                                                const uint32_t* b) {
    asm volatile(
        "mma.sync.aligned.m16n8k8.row.col.f32.tf32.tf32.f32 "
        "{%0,%1,%2,%3}, {%4,%5,%6,%7}, {%8,%9}, {%0,%1,%2,%3};"
        : "+f"(d[0]), "+f"(d[1]), "+f"(d[2]), "+f"(d[3])
        : "r"(a[0]), "r"(a[1]), "r"(a[2]), "r"(a[3]),
          "r"(b[0]), "r"(b[1]));
}

static __device__ __forceinline__ float sqrt_approx(float v) {
    float r;
    asm("sqrt.approx.f32 %0, %1;" : "=f"(r) : "f"(v));
    return r;
}

__global__ __launch_bounds__(NTH, 2)
void som_mma_kernel(const float* __restrict__ x,
                    const float* __restrict__ w,
                    float* __restrict__ out,
                    int B, int N)
{
    __shared__ float sX[TILE_M * SP];   // tf32-rounded x tile; reused as C stage
    __shared__ float sW[TILE_N * SP];   // tf32-rounded w tile
    __shared__ float xs2[TILE_M];
    __shared__ float ws2[TILE_N];

    const int tid = threadIdx.x;
    const int n0  = blockIdx.x * TILE_N;
    const int m0  = blockIdx.y * TILE_M;

    // ---- Stage x tile (tf32-rounded) + fused row norms via shfl ----
    // Each iteration: 256 threads cover 32 rows (8 threads/row, float4 each).
    #pragma unroll
    for (int i = 0; i < (TILE_M * DD) / (4 * NTH); ++i) {
        int f4  = tid + i * NTH;
        int row = f4 >> 3;
        int c4  = f4 & 7;
        int gm  = m0 + row;
        float4 v = make_float4(0.f, 0.f, 0.f, 0.f);
        if (gm < B)
            v = *reinterpret_cast<const float4*>(x + (size_t)gm * DD + c4 * 4);
        uint4 t;
        t.x = f2tf32(v.x); t.y = f2tf32(v.y); t.z = f2tf32(v.z); t.w = f2tf32(v.w);
        *reinterpret_cast<uint4*>(&sX[row * SP + c4 * 4]) = t;
        // norm partial from ROUNDED values
        float a0 = __uint_as_float(t.x), a1 = __uint_as_float(t.y);
        float a2 = __uint_as_float(t.z), a3 = __uint_as_float(t.w);
        float s = fmaf(a0, a0, fmaf(a1, a1, fmaf(a2, a2, a3 * a3)));
        s += __shfl_xor_sync(0xffffffffu, s, 1);
        s += __shfl_xor_sync(0xffffffffu, s, 2);
        s += __shfl_xor_sync(0xffffffffu, s, 4);
        if (c4 == 0) xs2[row] = s;
    }
    // ---- Stage w tile (tf32-rounded, zero-fill past N) + fused norms ----
    #pragma unroll
    for (int i = 0; i < (TILE_N * DD) / (4 * NTH); ++i) {
        int f4  = tid + i * NTH;
        int row = f4 >> 3;
        int c4  = f4 & 7;
        int gn  = n0 + row;
        float4 v = make_float4(0.f, 0.f, 0.f, 0.f);
        if (gn < N)
            v = *reinterpret_cast<const float4*>(w + (size_t)gn * DD + c4 * 4);
        uint4 t;
        t.x = f2tf32(v.x); t.y = f2tf32(v.y); t.z = f2tf32(v.z); t.w = f2tf32(v.w);
        *reinterpret_cast<uint4*>(&sW[row * SP + c4 * 4]) = t;
        float a0 = __uint_as_float(t.x), a1 = __uint_as_float(t.y);
        float a2 = __uint_as_float(t.z), a3 = __uint_as_float(t.w);
        float s = fmaf(a0, a0, fmaf(a1, a1, fmaf(a2, a2, a3 * a3)));
        s += __shfl_xor_sync(0xffffffffu, s, 1);
        s += __shfl_xor_sync(0xffffffffu, s, 2);
        s += __shfl_xor_sync(0xffffffffu, s, 4);
        if (c4 == 0) ws2[row] = s;
    }
    __syncthreads();

    // ---- Warp tiling: 2(M) x 4(N) warps; warp tile 64x32 = 4x4 m16n8k8 ----
    // k-permutation: fragment col c maps to global k = (c<4) ? 2c : 2(c-4)+1,
    // identically for A and B => dot product unchanged, pairs become LDS.64.
    const int lane = tid & 31;
    const int wid  = tid >> 5;
    const int wm   = wid & 1;          // M offset wm*64
    const int wn   = wid >> 1;         // N offset wn*32
    const int g    = lane >> 2;        // group id
    const int t    = lane & 3;         // thread in group

    const uint32_t* uX = reinterpret_cast<const uint32_t*>(sX);
    const uint32_t* uW = reinterpret_cast<const uint32_t*>(sW);

    float acc[4][4][4];
    #pragma unroll
    for (int ma = 0; ma < 4; ++ma)
        #pragma unroll
        for (int na = 0; na < 4; ++na)
            #pragma unroll
            for (int r = 0; r < 4; ++r)
                acc[ma][na][r] = 0.f;

    #pragma unroll
    for (int ks = 0; ks < 4; ++ks) {
        const int kc = ks * 8 + 2 * t;   // adjacent pair (k, k+1)
        uint32_t afr[4][4];
        #pragma unroll
        for (int ma = 0; ma < 4; ++ma) {
            int r = wm * 64 + ma * 16 + g;
            uint2 lo = *reinterpret_cast<const uint2*>(&uX[r * SP + kc]);
            uint2 hi = *reinterpret_cast<const uint2*>(&uX[(r + 8) * SP + kc]);
            afr[ma][0] = lo.x;   // col t    -> k=kc
            afr[ma][2] = lo.y;   // col t+4  -> k=kc+1
            afr[ma][1] = hi.x;
            afr[ma][3] = hi.y;
        }
        uint32_t bfr[4][2];
        #pragma unroll
        for (int na = 0; na < 4; ++na) {
            int c = wn * 32 + na * 8 + g;
            uint2 bb = *reinterpret_cast<const uint2*>(&uW[c * SP + kc]);
            bfr[na][0] = bb.x;
            bfr[na][1] = bb.y;
        }
        #pragma unroll
        for (int ma = 0; ma < 4; ++ma)
            #pragma unroll
            for (int na = 0; na < 4; ++na)
                mma_tf32(acc[ma][na], afr[ma], bfr[na]);
    }

    // ---- Epilogue: restage 16x32 chunks in smem, packed STG.128 out ----
    __syncthreads();                         // sX/sW tiles dead -> reuse sX
    float* st = sX + wid * (16 * SP);        // per-warp 16x40 stage (fits sX)

    const int srow = lane >> 3;              // 0..3
    const int c4   = (lane & 7) * 4;         // 0..28
    const float4 w2 = *reinterpret_cast<const float4*>(&ws2[wn * 32 + c4]);
    const int gc = n0 + wn * 32 + c4;        // multiple of 4 -> all-or-none vs N
    const bool nok = gc < N;

    #pragma unroll
    for (int ma = 0; ma < 4; ++ma) {
        #pragma unroll
        for (int na = 0; na < 4; ++na) {
            const int c = na * 8 + 2 * t;
            *reinterpret_cast<float2*>(&st[g * SP + c]) =
                make_float2(acc[ma][na][0], acc[ma][na][1]);
            *reinterpret_cast<float2*>(&st[(g + 8) * SP + c]) =
                make_float2(acc[ma][na][2], acc[ma][na][3]);
        }
        __syncwarp();
        #pragma unroll
        for (int it = 0; it < 4; ++it) {
            const int lr = it * 4 + srow;
            const int mi = wm * 64 + ma * 16 + lr;
            const int gm = m0 + mi;
            const float x2 = xs2[mi];
            float4 cr = *reinterpret_cast<const float4*>(&st[lr * SP + c4]);
            float4 d;
            d.x = sqrt_approx(fmaxf(fmaf(-2.f, cr.x, x2 + w2.x), 0.f));
            d.y = sqrt_approx(fmaxf(fmaf(-2.f, cr.y, x2 + w2.y), 0.f));
            d.z = sqrt_approx(fmaxf(fmaf(-2.f, cr.z, x2 + w2.z), 0.f));
            d.w = sqrt_approx(fmaxf(fmaf(-2.f, cr.w, x2 + w2.w), 0.f));
            if (nok && gm < B)
                *reinterpret_cast<float4*>(out + (size_t)gm * N + gc) = d;
        }
        __syncwarp();
    }
}

extern "C" void kernel_launch(void* const* d_in, const int* in_sizes, int n_in,
                              void* d_out, int out_size)
{
    const float* x = (const float*)d_in[0];   // [B, 32]
    const float* w = (const float*)d_in[1];   // [N, 32]
    float* out = (float*)d_out;               // [B, N]

    int B = in_sizes[0] / DD;
    int N = in_sizes[1] / DD;

    dim3 grid((N + TILE_N - 1) / TILE_N, (B + TILE_M - 1) / TILE_M);
    som_mma_kernel<<<grid, NTH>>>(x, w, out, B, N);
}

// round 8
// speedup vs baseline: 2.0436x; 1.0012x over previous
#include <cuda_runtime.h>
#include <cstdint>

// KohonenSOM pairwise L2 distance via warp-level tf32 mma.sync.
// out[b][n] = sqrt(max(||x_b||^2 + ||w_n||^2 - 2 x_b.w_n, 0))
// Inputs rounded to tf32 at smem-stage; norms computed from ROUNDED values.
//
// CTA tile 128x128, K=32, 8 warps (2M x 4N), warp tile 64x32 = 4x4 m16n8k8.
// R6: (a) k-permutation so fragment pairs are smem-adjacent -> LDS.64 loads
//     (mainloop LDS instr count halved; pitch 40 => conflict-free);
//     (b) norms computed during staging via 8-lane shfl butterfly (no LDS pass);
//     (c) R5 packed STG.128 epilogue kept.

#define TILE_M 128
#define TILE_N 128
#define DD 32
#define NTH 256
#define SP 40   // smem row pitch in floats: conflict-free LDS.64 fragment loads

static __device__ __forceinline__ uint32_t f2tf32(float f) {
    uint32_t r;
    asm("cvt.rna.tf32.f32 %0, %1;" : "=r"(r) : "f"(f));
    return r;
}

static __device__ __forceinline__ void mma_tf32(float* d,
                                                const uint32_t* a,
                                                const uint32_t* b) {
    asm volatile(
        "mma.sync.aligned.m16n8k8.row.col.f32.tf32.tf32.f32 "
        "{%0,%1,%2,%3}, {%4,%5,%6,%7}, {%8,%9}, {%0,%1,%2,%3};"
        : "+f"(d[0]), "+f"(d[1]), "+f"(d[2]), "+f"(d[3])
        : "r"(a[0]), "r"(a[1]), "r"(a[2]), "r"(a[3]),
          "r"(b[0]), "r"(b[1]));
}

static __device__ __forceinline__ float sqrt_approx(float v) {
    float r;
    asm("sqrt.approx.f32 %0, %1;" : "=f"(r) : "f"(v));
    return r;
}

__global__ __launch_bounds__(NTH, 2)
void som_mma_kernel(const float* __restrict__ x,
                    const float* __restrict__ w,
                    float* __restrict__ out,
                    int B, int N)
{
    __shared__ float sX[TILE_M * SP];   // tf32-rounded x tile; reused as C stage
    __shared__ float sW[TILE_N * SP];   // tf32-rounded w tile
    __shared__ float xs2[TILE_M];
    __shared__ float ws2[TILE_N];

    const int tid = threadIdx.x;
    const int n0  = blockIdx.x * TILE_N;
    const int m0  = blockIdx.y * TILE_M;

    // ---- Stage x tile (tf32-rounded) + fused row norms via shfl ----
    // Each iteration: 256 threads cover 32 rows (8 threads/row, float4 each).
    #pragma unroll
    for (int i = 0; i < (TILE_M * DD) / (4 * NTH); ++i) {
        int f4  = tid + i * NTH;
        int row = f4 >> 3;
        int c4  = f4 & 7;
        int gm  = m0 + row;
        float4 v = make_float4(0.f, 0.f, 0.f, 0.f);
        if (gm < B)
            v = *reinterpret_cast<const float4*>(x + (size_t)gm * DD + c4 * 4);
        uint4 t;
        t.x = f2tf32(v.x); t.y = f2tf32(v.y); t.z = f2tf32(v.z); t.w = f2tf32(v.w);
        *reinterpret_cast<uint4*>(&sX[row * SP + c4 * 4]) = t;
        // norm partial from ROUNDED values
        float a0 = __uint_as_float(t.x), a1 = __uint_as_float(t.y);
        float a2 = __uint_as_float(t.z), a3 = __uint_as_float(t.w);
        float s = fmaf(a0, a0, fmaf(a1, a1, fmaf(a2, a2, a3 * a3)));
        s += __shfl_xor_sync(0xffffffffu, s, 1);
        s += __shfl_xor_sync(0xffffffffu, s, 2);
        s += __shfl_xor_sync(0xffffffffu, s, 4);
        if (c4 == 0) xs2[row] = s;
    }
    // ---- Stage w tile (tf32-rounded, zero-fill past N) + fused norms ----
    #pragma unroll
    for (int i = 0; i < (TILE_N * DD) / (4 * NTH); ++i) {
        int f4  = tid + i * NTH;
        int row = f4 >> 3;
        int c4  = f4 & 7;
        int gn  = n0 + row;
        float4 v = make_float4(0.f, 0.f, 0.f, 0.f);
        if (gn < N)
            v = *reinterpret_cast<const float4*>(w + (size_t)gn * DD + c4 * 4);
        uint4 t;
        t.x = f2tf32(v.x); t.y = f2tf32(v.y); t.z = f2tf32(v.z); t.w = f2tf32(v.w);
        *reinterpret_cast<uint4*>(&sW[row * SP + c4 * 4]) = t;
        float a0 = __uint_as_float(t.x), a1 = __uint_as_float(t.y);
        float a2 = __uint_as_float(t.z), a3 = __uint_as_float(t.w);
        float s = fmaf(a0, a0, fmaf(a1, a1, fmaf(a2, a2, a3 * a3)));
        s += __shfl_xor_sync(0xffffffffu, s, 1);
        s += __shfl_xor_sync(0xffffffffu, s, 2);
        s += __shfl_xor_sync(0xffffffffu, s, 4);
        if (c4 == 0) ws2[row] = s;
    }
    __syncthreads();

    // ---- Warp tiling: 2(M) x 4(N) warps; warp tile 64x32 = 4x4 m16n8k8 ----
    // k-permutation: fragment col c maps to global k = (c<4) ? 2c : 2(c-4)+1,
    // identically for A and B => dot product unchanged, pairs become LDS.64.
    const int lane = tid & 31;
    const int wid  = tid >> 5;
    const int wm   = wid & 1;          // M offset wm*64
    const int wn   = wid >> 1;         // N offset wn*32
    const int g    = lane >> 2;        // group id
    const int t    = lane & 3;         // thread in group

    const uint32_t* uX = reinterpret_cast<const uint32_t*>(sX);
    const uint32_t* uW = reinterpret_cast<const uint32_t*>(sW);

    float acc[4][4][4];
    #pragma unroll
    for (int ma = 0; ma < 4; ++ma)
        #pragma unroll
        for (int na = 0; na < 4; ++na)
            #pragma unroll
            for (int r = 0; r < 4; ++r)
                acc[ma][na][r] = 0.f;

    #pragma unroll
    for (int ks = 0; ks < 4; ++ks) {
        const int kc = ks * 8 + 2 * t;   // adjacent pair (k, k+1)
        uint32_t afr[4][4];
        #pragma unroll
        for (int ma = 0; ma < 4; ++ma) {
            int r = wm * 64 + ma * 16 + g;
            uint2 lo = *reinterpret_cast<const uint2*>(&uX[r * SP + kc]);
            uint2 hi = *reinterpret_cast<const uint2*>(&uX[(r + 8) * SP + kc]);
            afr[ma][0] = lo.x;   // col t    -> k=kc
            afr[ma][2] = lo.y;   // col t+4  -> k=kc+1
            afr[ma][1] = hi.x;
            afr[ma][3] = hi.y;
        }
        uint32_t bfr[4][2];
        #pragma unroll
        for (int na = 0; na < 4; ++na) {
            int c = wn * 32 + na * 8 + g;
            uint2 bb = *reinterpret_cast<const uint2*>(&uW[c * SP + kc]);
            bfr[na][0] = bb.x;
            bfr[na][1] = bb.y;
        }
        #pragma unroll
        for (int ma = 0; ma < 4; ++ma)
            #pragma unroll
            for (int na = 0; na < 4; ++na)
                mma_tf32(acc[ma][na], afr[ma], bfr[na]);
    }

    // ---- Epilogue: restage 16x32 chunks in smem, packed STG.128 out ----
    __syncthreads();                         // sX/sW tiles dead -> reuse sX
    float* st = sX + wid * (16 * SP);        // per-warp 16x40 stage (fits sX)

    const int srow = lane >> 3;              // 0..3
    const int c4   = (lane & 7) * 4;         // 0..28
    const float4 w2 = *reinterpret_cast<const float4*>(&ws2[wn * 32 + c4]);
    const int gc = n0 + wn * 32 + c4;        // multiple of 4 -> all-or-none vs N
    const bool nok = gc < N;

    #pragma unroll
    for (int ma = 0; ma < 4; ++ma) {
        #pragma unroll
        for (int na = 0; na < 4; ++na) {
            const int c = na * 8 + 2 * t;
            *reinterpret_cast<float2*>(&st[g * SP + c]) =
                make_float2(acc[ma][na][0], acc[ma][na][1]);
            *reinterpret_cast<float2*>(&st[(g + 8) * SP + c]) =
                make_float2(acc[ma][na][2], acc[ma][na][3]);
        }
        __syncwarp();
        #pragma unroll
        for (int it = 0; it < 4; ++it) {
            const int lr = it * 4 + srow;
            const int mi = wm * 64 + ma * 16 + lr;
            const int gm = m0 + mi;
            const float x2 = xs2[mi];
            float4 cr = *reinterpret_cast<const float4*>(&st[lr * SP + c4]);
            float4 d;
            d.x = sqrt_approx(fmaxf(fmaf(-2.f, cr.x, x2 + w2.x), 0.f));
            d.y = sqrt_approx(fmaxf(fmaf(-2.f, cr.y, x2 + w2.y), 0.f));
            d.z = sqrt_approx(fmaxf(fmaf(-2.f, cr.z, x2 + w2.z), 0.f));
            d.w = sqrt_approx(fmaxf(fmaf(-2.f, cr.w, x2 + w2.w), 0.f));
            if (nok && gm < B)
                *reinterpret_cast<float4*>(out + (size_t)gm * N + gc) = d;
        }
        __syncwarp();
    }
}

extern "C" void kernel_launch(void* const* d_in, const int* in_sizes, int n_in,
                              void* d_out, int out_size)
{
    const float* x = (const float*)d_in[0];   // [B, 32]
    const float* w = (const float*)d_in[1];   // [N, 32]
    float* out = (float*)d_out;               // [B, N]

    int B = in_sizes[0] / DD;
    int N = in_sizes[1] / DD;

    dim3 grid((N + TILE_N - 1) / TILE_N, (B + TILE_M - 1) / TILE_M);
    som_mma_kernel<<<grid, NTH>>>(x, w, out, B, N);
}

// round 10
// speedup vs baseline: 2.0454x; 1.0009x over previous
#include <cuda_runtime.h>
#include <cstdint>

// KohonenSOM pairwise L2 distance via warp-level tf32 mma.sync.
// out[b][n] = sqrt(max(||x_b||^2 + ||w_n||^2 - 2 x_b.w_n, 0))
// Inputs rounded to tf32 at smem-stage; norms computed from ROUNDED values.
//
// CTA tile 128x128, K=32, 8 warps (2M x 4N), warp tile 64x32 = 4x4 m16n8k8.
// R6: (a) k-permutation so fragment pairs are smem-adjacent -> LDS.64 loads
//     (mainloop LDS instr count halved; pitch 40 => conflict-free);
//     (b) norms computed during staging via 8-lane shfl butterfly (no LDS pass);
//     (c) R5 packed STG.128 epilogue kept.

#define TILE_M 128
#define TILE_N 128
#define DD 32
#define NTH 256
#define SP 40   // smem row pitch in floats: conflict-free LDS.64 fragment loads

static __device__ __forceinline__ uint32_t f2tf32(float f) {
    uint32_t r;
    asm("cvt.rna.tf32.f32 %0, %1;" : "=r"(r) : "f"(f));
    return r;
}

static __device__ __forceinline__ void mma_tf32(float* d,
                                                const uint32_t* a,
                                                const uint32_t* b) {
    asm volatile(
        "mma.sync.aligned.m16n8k8.row.col.f32.tf32.tf32.f32 "
        "{%0,%1,%2,%3}, {%4,%5,%6,%7}, {%8,%9}, {%0,%1,%2,%3};"
        : "+f"(d[0]), "+f"(d[1]), "+f"(d[2]), "+f"(d[3])
        : "r"(a[0]), "r"(a[1]), "r"(a[2]), "r"(a[3]),
          "r"(b[0]), "r"(b[1]));
}

static __device__ __forceinline__ float sqrt_approx(float v) {
    float r;
    asm("sqrt.approx.f32 %0, %1;" : "=f"(r) : "f"(v));
    return r;
}

__global__ __launch_bounds__(NTH, 2)
void som_mma_kernel(const float* __restrict__ x,
                    const float* __restrict__ w,
                    float* __restrict__ out,
                    int B, int N)
{
    __shared__ float sX[TILE_M * SP];   // tf32-rounded x tile; reused as C stage
    __shared__ float sW[TILE_N * SP];   // tf32-rounded w tile
    __shared__ float xs2[TILE_M];
    __shared__ float ws2[TILE_N];

    const int tid = threadIdx.x;
    const int n0  = blockIdx.x * TILE_N;
    const int m0  = blockIdx.y * TILE_M;

    // ---- Stage x tile (tf32-rounded) + fused row norms via shfl ----
    // Each iteration: 256 threads cover 32 rows (8 threads/row, float4 each).
    #pragma unroll
    for (int i = 0; i < (TILE_M * DD) / (4 * NTH); ++i) {
        int f4  = tid + i * NTH;
        int row = f4 >> 3;
        int c4  = f4 & 7;
        int gm  = m0 + row;
        float4 v = make_float4(0.f, 0.f, 0.f, 0.f);
        if (gm < B)
            v = *reinterpret_cast<const float4*>(x + (size_t)gm * DD + c4 * 4);
        uint4 t;
        t.x = f2tf32(v.x); t.y = f2tf32(v.y); t.z = f2tf32(v.z); t.w = f2tf32(v.w);
        *reinterpret_cast<uint4*>(&sX[row * SP + c4 * 4]) = t;
        // norm partial from ROUNDED values
        float a0 = __uint_as_float(t.x), a1 = __uint_as_float(t.y);
        float a2 = __uint_as_float(t.z), a3 = __uint_as_float(t.w);
        float s = fmaf(a0, a0, fmaf(a1, a1, fmaf(a2, a2, a3 * a3)));
        s += __shfl_xor_sync(0xffffffffu, s, 1);
        s += __shfl_xor_sync(0xffffffffu, s, 2);
        s += __shfl_xor_sync(0xffffffffu, s, 4);
        if (c4 == 0) xs2[row] = s;
    }
    // ---- Stage w tile (tf32-rounded, zero-fill past N) + fused norms ----
    #pragma unroll
    for (int i = 0; i < (TILE_N * DD) / (4 * NTH); ++i) {
        int f4  = tid + i * NTH;
        int row = f4 >> 3;
        int c4  = f4 & 7;
        int gn  = n0 + row;
        float4 v = make_float4(0.f, 0.f, 0.f, 0.f);
        if (gn < N)
            v = *reinterpret_cast<const float4*>(w + (size_t)gn * DD + c4 * 4);
        uint4 t;
        t.x = f2tf32(v.x); t.y = f2tf32(v.y); t.z = f2tf32(v.z); t.w = f2tf32(v.w);
        *reinterpret_cast<uint4*>(&sW[row * SP + c4 * 4]) = t;
        float a0 = __uint_as_float(t.x), a1 = __uint_as_float(t.y);
        float a2 = __uint_as_float(t.z), a3 = __uint_as_float(t.w);
        float s = fmaf(a0, a0, fmaf(a1, a1, fmaf(a2, a2, a3 * a3)));
        s += __shfl_xor_sync(0xffffffffu, s, 1);
        s += __shfl_xor_sync(0xffffffffu, s, 2);
        s += __shfl_xor_sync(0xffffffffu, s, 4);
        if (c4 == 0) ws2[row] = s;
    }
    __syncthreads();

    // ---- Warp tiling: 2(M) x 4(N) warps; warp tile 64x32 = 4x4 m16n8k8 ----
    // k-permutation: fragment col c maps to global k = (c<4) ? 2c : 2(c-4)+1,
    // identically for A and B => dot product unchanged, pairs become LDS.64.
    const int lane = tid & 31;
    const int wid  = tid >> 5;
    const int wm   = wid & 1;          // M offset wm*64
    const int wn   = wid >> 1;         // N offset wn*32
    const int g    = lane >> 2;        // group id
    const int t    = lane & 3;         // thread in group

    const uint32_t* uX = reinterpret_cast<const uint32_t*>(sX);
    const uint32_t* uW = reinterpret_cast<const uint32_t*>(sW);

    float acc[4][4][4];
    #pragma unroll
    for (int ma = 0; ma < 4; ++ma)
        #pragma unroll
        for (int na = 0; na < 4; ++na)
            #pragma unroll
            for (int r = 0; r < 4; ++r)
                acc[ma][na][r] = 0.f;

    #pragma unroll
    for (int ks = 0; ks < 4; ++ks) {
        const int kc = ks * 8 + 2 * t;   // adjacent pair (k, k+1)
        uint32_t afr[4][4];
        #pragma unroll
        for (int ma = 0; ma < 4; ++ma) {
            int r = wm * 64 + ma * 16 + g;
            uint2 lo = *reinterpret_cast<const uint2*>(&uX[r * SP + kc]);
            uint2 hi = *reinterpret_cast<const uint2*>(&uX[(r + 8) * SP + kc]);
            afr[ma][0] = lo.x;   // col t    -> k=kc
            afr[ma][2] = lo.y;   // col t+4  -> k=kc+1
            afr[ma][1] = hi.x;
            afr[ma][3] = hi.y;
        }
        uint32_t bfr[4][2];
        #pragma unroll
        for (int na = 0; na < 4; ++na) {
            int c = wn * 32 + na * 8 + g;
            uint2 bb = *reinterpret_cast<const uint2*>(&uW[c * SP + kc]);
            bfr[na][0] = bb.x;
            bfr[na][1] = bb.y;
        }
        #pragma unroll
        for (int ma = 0; ma < 4; ++ma)
            #pragma unroll
            for (int na = 0; na < 4; ++na)
                mma_tf32(acc[ma][na], afr[ma], bfr[na]);
    }

    // ---- Epilogue: restage 16x32 chunks in smem, packed STG.128 out ----
    __syncthreads();                         // sX/sW tiles dead -> reuse sX
    float* st = sX + wid * (16 * SP);        // per-warp 16x40 stage (fits sX)

    const int srow = lane >> 3;              // 0..3
    const int c4   = (lane & 7) * 4;         // 0..28
    const float4 w2 = *reinterpret_cast<const float4*>(&ws2[wn * 32 + c4]);
    const int gc = n0 + wn * 32 + c4;        // multiple of 4 -> all-or-none vs N
    const bool nok = gc < N;

    #pragma unroll
    for (int ma = 0; ma < 4; ++ma) {
        #pragma unroll
        for (int na = 0; na < 4; ++na) {
            const int c = na * 8 + 2 * t;
            *reinterpret_cast<float2*>(&st[g * SP + c]) =
                make_float2(acc[ma][na][0], acc[ma][na][1]);
            *reinterpret_cast<float2*>(&st[(g + 8) * SP + c]) =
                make_float2(acc[ma][na][2], acc[ma][na][3]);
        }
        __syncwarp();
        #pragma unroll
        for (int it = 0; it < 4; ++it) {
            const int lr = it * 4 + srow;
            const int mi = wm * 64 + ma * 16 + lr;
            const int gm = m0 + mi;
            const float x2 = xs2[mi];
            float4 cr = *reinterpret_cast<const float4*>(&st[lr * SP + c4]);
            float4 d;
            d.x = sqrt_approx(fmaxf(fmaf(-2.f, cr.x, x2 + w2.x), 0.f));
            d.y = sqrt_approx(fmaxf(fmaf(-2.f, cr.y, x2 + w2.y), 0.f));
            d.z = sqrt_approx(fmaxf(fmaf(-2.f, cr.z, x2 + w2.z), 0.f));
            d.w = sqrt_approx(fmaxf(fmaf(-2.f, cr.w, x2 + w2.w), 0.f));
            if (nok && gm < B)
                *reinterpret_cast<float4*>(out + (size_t)gm * N + gc) = d;
        }
        __syncwarp();
    }
}

extern "C" void kernel_launch(void* const* d_in, const int* in_sizes, int n_in,
                              void* d_out, int out_size)
{
    const float* x = (const float*)d_in[0];   // [B, 32]
    const float* w = (const float*)d_in[1];   // [N, 32]
    float* out = (float*)d_out;               // [B, N]

    int B = in_sizes[0] / DD;
    int N = in_sizes[1] / DD;

    dim3 grid((N + TILE_N - 1) / TILE_N, (B + TILE_M - 1) / TILE_M);
    som_mma_kernel<<<grid, NTH>>>(x, w, out, B, N);
}

// round 11
// speedup vs baseline: 2.0462x; 1.0004x over previous
#include <cuda_runtime.h>
#include <cstdint>

// KohonenSOM pairwise L2 distance via warp-level tf32 mma.sync.
// out[b][n] = sqrt(max(||x_b||^2 + ||w_n||^2 - 2 x_b.w_n, 0))
// Inputs rounded to tf32 at smem-stage; norms computed from ROUNDED values.
//
// CTA tile 128x128, K=32, 8 warps (2M x 4N), warp tile 64x32 = 4x4 m16n8k8.
// R6: (a) k-permutation so fragment pairs are smem-adjacent -> LDS.64 loads
//     (mainloop LDS instr count halved; pitch 40 => conflict-free);
//     (b) norms computed during staging via 8-lane shfl butterfly (no LDS pass);
//     (c) R5 packed STG.128 epilogue kept.

#define TILE_M 128
#define TILE_N 128
#define DD 32
#define NTH 256
#define SP 40   // smem row pitch in floats: conflict-free LDS.64 fragment loads

static __device__ __forceinline__ uint32_t f2tf32(float f) {
    uint32_t r;
    asm("cvt.rna.tf32.f32 %0, %1;" : "=r"(r) : "f"(f));
    return r;
}

static __device__ __forceinline__ void mma_tf32(float* d,
                                                const uint32_t* a,
                                                const uint32_t* b) {
    asm volatile(
        "mma.sync.aligned.m16n8k8.row.col.f32.tf32.tf32.f32 "
        "{%0,%1,%2,%3}, {%4,%5,%6,%7}, {%8,%9}, {%0,%1,%2,%3};"
        : "+f"(d[0]), "+f"(d[1]), "+f"(d[2]), "+f"(d[3])
        : "r"(a[0]), "r"(a[1]), "r"(a[2]), "r"(a[3]),
          "r"(b[0]), "r"(b[1]));
}

static __device__ __forceinline__ float sqrt_approx(float v) {
    float r;
    asm("sqrt.approx.f32 %0, %1;" : "=f"(r) : "f"(v));
    return r;
}

__global__ __launch_bounds__(NTH, 2)
void som_mma_kernel(const float* __restrict__ x,
                    const float* __restrict__ w,
                    float* __restrict__ out,
                    int B, int N)
{
    __shared__ float sX[TILE_M * SP];   // tf32-rounded x tile; reused as C stage
    __shared__ float sW[TILE_N * SP];   // tf32-rounded w tile
    __shared__ float xs2[TILE_M];
    __shared__ float ws2[TILE_N];

    const int tid = threadIdx.x;
    const int n0  = blockIdx.x * TILE_N;
    const int m0  = blockIdx.y * TILE_M;

    // ---- Stage x tile (tf32-rounded) + fused row norms via shfl ----
    // Each iteration: 256 threads cover 32 rows (8 threads/row, float4 each).
    #pragma unroll
    for (int i = 0; i < (TILE_M * DD) / (4 * NTH); ++i) {
        int f4  = tid + i * NTH;
        int row = f4 >> 3;
        int c4  = f4 & 7;
        int gm  = m0 + row;
        float4 v = make_float4(0.f, 0.f, 0.f, 0.f);
        if (gm < B)
            v = *reinterpret_cast<const float4*>(x + (size_t)gm * DD + c4 * 4);
        uint4 t;
        t.x = f2tf32(v.x); t.y = f2tf32(v.y); t.z = f2tf32(v.z); t.w = f2tf32(v.w);
        *reinterpret_cast<uint4*>(&sX[row * SP + c4 * 4]) = t;
        // norm partial from ROUNDED values
        float a0 = __uint_as_float(t.x), a1 = __uint_as_float(t.y);
        float a2 = __uint_as_float(t.z), a3 = __uint_as_float(t.w);
        float s = fmaf(a0, a0, fmaf(a1, a1, fmaf(a2, a2, a3 * a3)));
        s += __shfl_xor_sync(0xffffffffu, s, 1);
        s += __shfl_xor_sync(0xffffffffu, s, 2);
        s += __shfl_xor_sync(0xffffffffu, s, 4);
        if (c4 == 0) xs2[row] = s;
    }
    // ---- Stage w tile (tf32-rounded, zero-fill past N) + fused norms ----
    #pragma unroll
    for (int i = 0; i < (TILE_N * DD) / (4 * NTH); ++i) {
        int f4  = tid + i * NTH;
        int row = f4 >> 3;
        int c4  = f4 & 7;
        int gn  = n0 + row;
        float4 v = make_float4(0.f, 0.f, 0.f, 0.f);
        if (gn < N)
            v = *reinterpret_cast<const float4*>(w + (size_t)gn * DD + c4 * 4);
        uint4 t;
        t.x = f2tf32(v.x); t.y = f2tf32(v.y); t.z = f2tf32(v.z); t.w = f2tf32(v.w);
        *reinterpret_cast<uint4*>(&sW[row * SP + c4 * 4]) = t;
        float a0 = __uint_as_float(t.x), a1 = __uint_as_float(t.y);
        float a2 = __uint_as_float(t.z), a3 = __uint_as_float(t.w);
        float s = fmaf(a0, a0, fmaf(a1, a1, fmaf(a2, a2, a3 * a3)));
        s += __shfl_xor_sync(0xffffffffu, s, 1);
        s += __shfl_xor_sync(0xffffffffu, s, 2);
        s += __shfl_xor_sync(0xffffffffu, s, 4);
        if (c4 == 0) ws2[row] = s;
    }
    __syncthreads();

    // ---- Warp tiling: 2(M) x 4(N) warps; warp tile 64x32 = 4x4 m16n8k8 ----
    // k-permutation: fragment col c maps to global k = (c<4) ? 2c : 2(c-4)+1,
    // identically for A and B => dot product unchanged, pairs become LDS.64.
    const int lane = tid & 31;
    const int wid  = tid >> 5;
    const int wm   = wid & 1;          // M offset wm*64
    const int wn   = wid >> 1;         // N offset wn*32
    const int g    = lane >> 2;        // group id
    const int t    = lane & 3;         // thread in group

    const uint32_t* uX = reinterpret_cast<const uint32_t*>(sX);
    const uint32_t* uW = reinterpret_cast<const uint32_t*>(sW);

    float acc[4][4][4];
    #pragma unroll
    for (int ma = 0; ma < 4; ++ma)
        #pragma unroll
        for (int na = 0; na < 4; ++na)
            #pragma unroll
            for (int r = 0; r < 4; ++r)
                acc[ma][na][r] = 0.f;

    #pragma unroll
    for (int ks = 0; ks < 4; ++ks) {
        const int kc = ks * 8 + 2 * t;   // adjacent pair (k, k+1)
        uint32_t afr[4][4];
        #pragma unroll
        for (int ma = 0; ma < 4; ++ma) {
            int r = wm * 64 + ma * 16 + g;
            uint2 lo = *reinterpret_cast<const uint2*>(&uX[r * SP + kc]);
            uint2 hi = *reinterpret_cast<const uint2*>(&uX[(r + 8) * SP + kc]);
            afr[ma][0] = lo.x;   // col t    -> k=kc
            afr[ma][2] = lo.y;   // col t+4  -> k=kc+1
            afr[ma][1] = hi.x;
            afr[ma][3] = hi.y;
        }
        uint32_t bfr[4][2];
        #pragma unroll
        for (int na = 0; na < 4; ++na) {
            int c = wn * 32 + na * 8 + g;
            uint2 bb = *reinterpret_cast<const uint2*>(&uW[c * SP + kc]);
            bfr[na][0] = bb.x;
            bfr[na][1] = bb.y;
        }
        #pragma unroll
        for (int ma = 0; ma < 4; ++ma)
            #pragma unroll
            for (int na = 0; na < 4; ++na)
                mma_tf32(acc[ma][na], afr[ma], bfr[na]);
    }

    // ---- Epilogue: restage 16x32 chunks in smem, packed STG.128 out ----
    __syncthreads();                         // sX/sW tiles dead -> reuse sX
    float* st = sX + wid * (16 * SP);        // per-warp 16x40 stage (fits sX)

    const int srow = lane >> 3;              // 0..3
    const int c4   = (lane & 7) * 4;         // 0..28
    const float4 w2 = *reinterpret_cast<const float4*>(&ws2[wn * 32 + c4]);
    const int gc = n0 + wn * 32 + c4;        // multiple of 4 -> all-or-none vs N
    const bool nok = gc < N;

    #pragma unroll
    for (int ma = 0; ma < 4; ++ma) {
        #pragma unroll
        for (int na = 0; na < 4; ++na) {
            const int c = na * 8 + 2 * t;
            *reinterpret_cast<float2*>(&st[g * SP + c]) =
                make_float2(acc[ma][na][0], acc[ma][na][1]);
            *reinterpret_cast<float2*>(&st[(g + 8) * SP + c]) =
                make_float2(acc[ma][na][2], acc[ma][na][3]);
        }
        __syncwarp();
        #pragma unroll
        for (int it = 0; it < 4; ++it) {
            const int lr = it * 4 + srow;
            const int mi = wm * 64 + ma * 16 + lr;
            const int gm = m0 + mi;
            const float x2 = xs2[mi];
            float4 cr = *reinterpret_cast<const float4*>(&st[lr * SP + c4]);
            float4 d;
            d.x = sqrt_approx(fmaxf(fmaf(-2.f, cr.x, x2 + w2.x), 0.f));
            d.y = sqrt_approx(fmaxf(fmaf(-2.f, cr.y, x2 + w2.y), 0.f));
            d.z = sqrt_approx(fmaxf(fmaf(-2.f, cr.z, x2 + w2.z), 0.f));
            d.w = sqrt_approx(fmaxf(fmaf(-2.f, cr.w, x2 + w2.w), 0.f));
            if (nok && gm < B)
                *reinterpret_cast<float4*>(out + (size_t)gm * N + gc) = d;
        }
        __syncwarp();
    }
}

extern "C" void kernel_launch(void* const* d_in, const int* in_sizes, int n_in,
                              void* d_out, int out_size)
{
    const float* x = (const float*)d_in[0];   // [B, 32]
    const float* w = (const float*)d_in[1];   // [N, 32]
    float* out = (float*)d_out;               // [B, N]

    int B = in_sizes[0] / DD;
    int N = in_sizes[1] / DD;

    dim3 grid((N + TILE_N - 1) / TILE_N, (B + TILE_M - 1) / TILE_M);
    som_mma_kernel<<<grid, NTH>>>(x, w, out, B, N);
}